// round 1
// baseline (speedup 1.0000x reference)
#include <cuda_runtime.h>
#include <math.h>

// ---------------------------------------------------------------------------
// RowWiseGatedAttention (AlphaFold MSA row attention w/ pair bias), fp32.
// B=1, c_m=256, s=128, i=256, H=8, c_head=32, c_z=128.
// ---------------------------------------------------------------------------

#define CM     256
#define S_DIM  128
#define I_DIM  256
#define NCOL   32768            // S_DIM * I_DIM
#define CZ     128
#define IJ     65536            // I_DIM * I_DIM
#define NH     8
#define CH     32
#define NTOT   8388608          // CM*NCOL == CZ*IJ
#define LN_EPS 1e-5f

// ---------------- scratch (static device globals; no allocation) -----------
__device__ float  g_x[(size_t)CM * NCOL];          // normalized msa  [c][s*i]
__device__ float  g_qkvg[(size_t)4 * CM * NCOL];   // q,k,v,g stacked [4*256][32768]
__device__ float  g_bias[(size_t)NH * IJ];         // pair bias       [h][i*j]
__device__ float  g_o[(size_t)CM * NCOL];          // gated attn out, p = c*8+h
__device__ float2 g_part[2][1024];                 // partial (sum, sumsq)
__device__ float  g_stats[4];                      // mu1, rs1, mu2, rs2

// ---------------- stage 1: partial reduction (sum, sumsq) ------------------
__global__ void __launch_bounds__(256) k_partial_reduce(const float* __restrict__ src, int which) {
    const float4* s4 = (const float4*)src;
    int t = blockIdx.x * 256 + threadIdx.x;        // 0..262143
    float s = 0.f, ss = 0.f;
#pragma unroll
    for (int k = 0; k < 8; k++) {
        float4 v = s4[t + k * 262144];
        s  += v.x + v.y + v.z + v.w;
        ss += v.x * v.x + v.y * v.y + v.z * v.z + v.w * v.w;
    }
    __shared__ float sh[256], sh2[256];
    int tid = threadIdx.x;
    sh[tid] = s; sh2[tid] = ss;
    __syncthreads();
    for (int off = 128; off; off >>= 1) {
        if (tid < off) { sh[tid] += sh[tid + off]; sh2[tid] += sh2[tid + off]; }
        __syncthreads();
    }
    if (tid == 0) g_part[which][blockIdx.x] = make_float2(sh[0], sh2[0]);
}

// ---------------- stage 2: finalize stats -----------------------------------
__global__ void __launch_bounds__(1024) k_finalize() {
    __shared__ float a0[1024], a1[1024], b0[1024], b1[1024];
    int t = threadIdx.x;
    float2 pa = g_part[0][t];
    float2 pb = g_part[1][t];
    a0[t] = pa.x; a1[t] = pa.y; b0[t] = pb.x; b1[t] = pb.y;
    __syncthreads();
    for (int off = 512; off; off >>= 1) {
        if (t < off) {
            a0[t] += a0[t + off]; a1[t] += a1[t + off];
            b0[t] += b0[t + off]; b1[t] += b1[t + off];
        }
        __syncthreads();
    }
    if (t == 0) {
        const float invN = 1.f / (float)NTOT;
        float mu1 = a0[0] * invN;
        float v1  = a1[0] * invN - mu1 * mu1;
        float mu2 = b0[0] * invN;
        float v2  = b1[0] * invN - mu2 * mu2;
        g_stats[0] = mu1; g_stats[1] = rsqrtf(v1 + LN_EPS);
        g_stats[2] = mu2; g_stats[3] = rsqrtf(v2 + LN_EPS);
    }
}

// ---------------- LN1 apply -> g_x ------------------------------------------
__global__ void __launch_bounds__(256) k_ln1(const float* __restrict__ msa,
                                             const float* __restrict__ w,
                                             const float* __restrict__ b) {
    int t = blockIdx.x * 256 + threadIdx.x;        // float4 index, 0..2097151
    float mu = g_stats[0], rs = g_stats[1];
    float4 m = ((const float4*)msa)[t];
    float4 ww = ((const float4*)w)[t];
    float4 bb = ((const float4*)b)[t];
    float4 o;
    o.x = (m.x - mu) * rs * ww.x + bb.x;
    o.y = (m.y - mu) * rs * ww.y + bb.y;
    o.z = (m.z - mu) * rs * ww.z + bb.z;
    o.w = (m.w - mu) * rs * ww.w + bb.w;
    ((float4*)g_x)[t] = o;
}

// ---------------- fused projection GEMM: [1024 x 256] @ [256 x 32768] ------
// rows 0..255 -> q, 256..511 -> k, 512..767 -> v, 768..1023 -> g (sigmoid+bg)
__global__ void __launch_bounds__(256) k_proj_gemm(const float* __restrict__ Wq,
                                                   const float* __restrict__ Wk,
                                                   const float* __restrict__ Wv,
                                                   const float* __restrict__ Wg,
                                                   const float* __restrict__ bg) {
    __shared__ float As[16][68];
    __shared__ float Bs[16][68];
    int tx = threadIdx.x, ty = threadIdx.y;
    int tid = ty * 16 + tx;
    int bm = blockIdx.y * 64, bn = blockIdx.x * 64;
    int wsel = bm >> 8;
    const float* W = (wsel == 0) ? Wq : (wsel == 1) ? Wk : (wsel == 2) ? Wv : Wg;
    int orow = bm & 255;
    float acc[4][4];
#pragma unroll
    for (int i = 0; i < 4; i++)
#pragma unroll
        for (int j = 0; j < 4; j++) acc[i][j] = 0.f;

    for (int k0 = 0; k0 < 256; k0 += 16) {
#pragma unroll
        for (int i = 0; i < 4; i++) {
            int e = tid + i * 256;
            int r = e >> 4, c = e & 15;
            As[c][r] = W[(orow + r) * 256 + k0 + c];
        }
#pragma unroll
        for (int i = 0; i < 4; i++) {
            int e = tid + i * 256;
            int cc = e >> 6, n = e & 63;
            Bs[cc][n] = g_x[(size_t)(k0 + cc) * NCOL + bn + n];
        }
        __syncthreads();
#pragma unroll
        for (int kk = 0; kk < 16; kk++) {
            float4 a4 = *(const float4*)&As[kk][ty * 4];
            float4 b4 = *(const float4*)&Bs[kk][tx * 4];
            float a[4] = {a4.x, a4.y, a4.z, a4.w};
            float b[4] = {b4.x, b4.y, b4.z, b4.w};
#pragma unroll
            for (int i = 0; i < 4; i++)
#pragma unroll
                for (int j = 0; j < 4; j++) acc[i][j] += a[i] * b[j];
        }
        __syncthreads();
    }
    bool isg = (wsel == 3);
#pragma unroll
    for (int i = 0; i < 4; i++) {
        int row = bm + ty * 4 + i;
        float bgv = isg ? bg[row & 255] : 0.f;
#pragma unroll
        for (int j = 0; j < 4; j++) {
            float v = acc[i][j];
            if (isg) v = 1.f / (1.f + __expf(-(v + bgv)));
            g_qkvg[(size_t)row * NCOL + bn + tx * 4 + j] = v;
        }
    }
}

// ---------------- pair bias: LN2 fused into Wb GEMV -------------------------
__global__ void __launch_bounds__(256) k_bias(const float* __restrict__ pair,
                                              const float* __restrict__ ln2w,
                                              const float* __restrict__ ln2b,
                                              const float* __restrict__ Wb) {
    __shared__ float wb_s[NH * CZ];
    int tid = threadIdx.x;
    for (int e = tid; e < NH * CZ; e += 256) wb_s[e] = Wb[e];
    __syncthreads();
    int col = blockIdx.x * 256 + tid;
    float mu = g_stats[2], rs = g_stats[3];
    float acc[NH];
#pragma unroll
    for (int o = 0; o < NH; o++) acc[o] = 0.f;
#pragma unroll 4
    for (int c = 0; c < CZ; c++) {
        size_t idx = (size_t)c * IJ + col;
        float z = (pair[idx] - mu) * rs * ln2w[idx] + ln2b[idx];
#pragma unroll
        for (int o = 0; o < NH; o++) acc[o] += wb_s[o * CZ + c] * z;
    }
#pragma unroll
    for (int o = 0; o < NH; o++) g_bias[(size_t)o * IJ + col] = acc[o];
}

// ---------------- attention: one block per (h, s) ---------------------------
// dyn smem: q[32][256] k[32][256] v[32][256] sc[64][260] o_s[32][64]
#define SC_STRIDE 260
#define ATTN_SMEM ((3 * 32 * 256 + 64 * SC_STRIDE + 32 * 64) * 4)

__global__ void __launch_bounds__(256, 1) k_attn() {
    extern __shared__ float sm[];
    float* q_s = sm;                  // 8192
    float* k_s = q_s + 32 * 256;      // 8192
    float* v_s = k_s + 32 * 256;      // 8192
    float* sc  = v_s + 32 * 256;      // 64*260
    float* o_s = sc + 64 * SC_STRIDE; // 2048

    int s = blockIdx.x, h = blockIdx.y;
    int tid = threadIdx.x;

    for (int e = tid; e < 32 * 256; e += 256) {
        int c = e >> 8, i = e & 255;
        size_t col = (size_t)s * 256 + i;
        q_s[e] = g_qkvg[((size_t)(0 * CM + h * 32 + c)) * NCOL + col];
        k_s[e] = g_qkvg[((size_t)(1 * CM + h * 32 + c)) * NCOL + col];
        v_s[e] = g_qkvg[((size_t)(2 * CM + h * 32 + c)) * NCOL + col];
    }
    __syncthreads();

    const float scale = 0.17677669529663687f;   // 1/sqrt(32)

    for (int i0 = 0; i0 < 256; i0 += 64) {
        // ---- scores: thread = column j, 64 rows in registers ----
        {
            int j = tid;
            float acc[64];
#pragma unroll
            for (int t = 0; t < 64; t++) acc[t] = 0.f;
#pragma unroll 4
            for (int c = 0; c < 32; c++) {
                float kv = k_s[c * 256 + j];
                const float4* q4p = (const float4*)&q_s[c * 256 + i0];
#pragma unroll
                for (int t4 = 0; t4 < 16; t4++) {
                    float4 q4 = q4p[t4];
                    acc[t4 * 4 + 0] += q4.x * kv;
                    acc[t4 * 4 + 1] += q4.y * kv;
                    acc[t4 * 4 + 2] += q4.z * kv;
                    acc[t4 * 4 + 3] += q4.w * kv;
                }
            }
#pragma unroll
            for (int t = 0; t < 64; t++) {
                float b = g_bias[(size_t)h * IJ + (size_t)(i0 + t) * 256 + j];
                sc[t * SC_STRIDE + j] = acc[t] * scale + b;
            }
        }
        __syncthreads();

        // ---- softmax rows: warp w owns rows w*8 .. w*8+7 ----
        {
            int lane = tid & 31, w = tid >> 5;
#pragma unroll
            for (int r = 0; r < 8; r++) {
                float* p = &sc[(w * 8 + r) * SC_STRIDE];
                float vals[8];
                float m = -1e30f;
#pragma unroll
                for (int u = 0; u < 8; u++) { vals[u] = p[lane + u * 32]; m = fmaxf(m, vals[u]); }
#pragma unroll
                for (int off = 16; off; off >>= 1) m = fmaxf(m, __shfl_xor_sync(0xffffffffu, m, off));
                float sum = 0.f;
#pragma unroll
                for (int u = 0; u < 8; u++) { vals[u] = __expf(vals[u] - m); sum += vals[u]; }
#pragma unroll
                for (int off = 16; off; off >>= 1) sum += __shfl_xor_sync(0xffffffffu, sum, off);
                float inv = 1.f / sum;
#pragma unroll
                for (int u = 0; u < 8; u++) p[lane + u * 32] = vals[u] * inv;
            }
        }
        __syncthreads();

        // ---- AV: thread c = tid>>3, ii = (tid&7) + 8t ----
        {
            int c = tid >> 3;
            int iw = tid & 7;
            float acc2[8];
#pragma unroll
            for (int t = 0; t < 8; t++) acc2[t] = 0.f;
#pragma unroll 4
            for (int jj = 0; jj < 256; jj += 4) {
                float4 v4 = *(const float4*)&v_s[c * 256 + jj];
#pragma unroll
                for (int t = 0; t < 8; t++) {
                    int ii = iw + t * 8;
                    float4 a4 = *(const float4*)&sc[ii * SC_STRIDE + jj];
                    acc2[t] += v4.x * a4.x + v4.y * a4.y + v4.z * a4.z + v4.w * a4.w;
                }
            }
#pragma unroll
            for (int t = 0; t < 8; t++) o_s[c * 64 + iw + t * 8] = acc2[t];
        }
        __syncthreads();

        // ---- gate + store (coalesced over i) ----
        for (int e = tid; e < 2048; e += 256) {
            int c2 = e >> 6, ii = e & 63;
            size_t col = (size_t)s * 256 + i0 + ii;
            float gv = g_qkvg[((size_t)(3 * CM + h * 32 + c2)) * NCOL + col];
            g_o[((size_t)(c2 * NH + h)) * NCOL + col] = o_s[c2 * 64 + ii] * gv;
        }
        __syncthreads();
    }
}

// ---------------- output GEMM: [256 x 256] @ [256 x 32768] + brep -----------
__global__ void __launch_bounds__(256) k_out_gemm(const float* __restrict__ Wrep,
                                                  const float* __restrict__ brep,
                                                  float* __restrict__ out) {
    __shared__ float As[16][68];
    __shared__ float Bs[16][68];
    int tx = threadIdx.x, ty = threadIdx.y;
    int tid = ty * 16 + tx;
    int bm = blockIdx.y * 64, bn = blockIdx.x * 64;
    float acc[4][4];
#pragma unroll
    for (int i = 0; i < 4; i++)
#pragma unroll
        for (int j = 0; j < 4; j++) acc[i][j] = 0.f;

    for (int k0 = 0; k0 < 256; k0 += 16) {
#pragma unroll
        for (int i = 0; i < 4; i++) {
            int e = tid + i * 256;
            int r = e >> 4, c = e & 15;
            As[c][r] = Wrep[(bm + r) * 256 + k0 + c];
        }
#pragma unroll
        for (int i = 0; i < 4; i++) {
            int e = tid + i * 256;
            int cc = e >> 6, n = e & 63;
            Bs[cc][n] = g_o[(size_t)(k0 + cc) * NCOL + bn + n];
        }
        __syncthreads();
#pragma unroll
        for (int kk = 0; kk < 16; kk++) {
            float4 a4 = *(const float4*)&As[kk][ty * 4];
            float4 b4 = *(const float4*)&Bs[kk][tx * 4];
            float a[4] = {a4.x, a4.y, a4.z, a4.w};
            float b[4] = {b4.x, b4.y, b4.z, b4.w};
#pragma unroll
            for (int i = 0; i < 4; i++)
#pragma unroll
                for (int j = 0; j < 4; j++) acc[i][j] += a[i] * b[j];
        }
        __syncthreads();
    }
#pragma unroll
    for (int i = 0; i < 4; i++) {
        int row = bm + ty * 4 + i;
        float bb = brep[row];
#pragma unroll
        for (int j = 0; j < 4; j++)
            out[(size_t)row * NCOL + bn + tx * 4 + j] = acc[i][j] + bb;
    }
}

// ---------------------------------------------------------------------------
extern "C" void kernel_launch(void* const* d_in, const int* in_sizes, int n_in,
                              void* d_out, int out_size) {
    const float* msa  = (const float*)d_in[0];
    const float* pair = (const float*)d_in[1];
    const float* ln1w = (const float*)d_in[2];
    const float* ln1b = (const float*)d_in[3];
    const float* ln2w = (const float*)d_in[4];
    const float* ln2b = (const float*)d_in[5];
    const float* Wq   = (const float*)d_in[6];
    const float* Wk   = (const float*)d_in[7];
    const float* Wv   = (const float*)d_in[8];
    const float* Wb   = (const float*)d_in[9];
    const float* Wg   = (const float*)d_in[10];
    const float* bg   = (const float*)d_in[11];
    const float* Wrep = (const float*)d_in[12];
    const float* brep = (const float*)d_in[13];
    float* out = (float*)d_out;

    // Opt-in to >48KB dynamic smem for the attention kernel. Query-then-set:
    // the set happens on the first (pre-capture) correctness call; during
    // graph capture only the (capture-safe) query runs.
    cudaFuncAttributes attr;
    cudaFuncGetAttributes(&attr, k_attn);
    if (attr.maxDynamicSharedSizeBytes < (int)ATTN_SMEM) {
        cudaFuncSetAttribute(k_attn, cudaFuncAttributeMaxDynamicSharedMemorySize, ATTN_SMEM);
    }

    k_partial_reduce<<<1024, 256>>>(msa, 0);
    k_partial_reduce<<<1024, 256>>>(pair, 1);
    k_finalize<<<1, 1024>>>();
    k_ln1<<<NTOT / 4 / 256, 256>>>(msa, ln1w, ln1b);
    k_proj_gemm<<<dim3(NCOL / 64, 1024 / 64), dim3(16, 16)>>>(Wq, Wk, Wv, Wg, bg);
    k_bias<<<IJ / 256, 256>>>(pair, ln2w, ln2b, Wb);
    k_attn<<<dim3(S_DIM, NH), 256, ATTN_SMEM>>>();
    k_out_gemm<<<dim3(NCOL / 64, 256 / 64), dim3(16, 16)>>>(Wrep, brep, out);
}

// round 2
// speedup vs baseline: 1.0003x; 1.0003x over previous
#include <cuda_runtime.h>
#include <math.h>

// ---------------------------------------------------------------------------
// RowWiseGatedAttention (AlphaFold MSA row attention w/ pair bias), fp32.
// B=1, c_m=256, s=128, i=256, H=8, c_head=32, c_z=128.
// ---------------------------------------------------------------------------

#define CM     256
#define S_DIM  128
#define I_DIM  256
#define NCOL   32768            // S_DIM * I_DIM
#define CZ     128
#define IJ     65536            // I_DIM * I_DIM
#define NH     8
#define CH     32
#define NTOT   8388608          // CM*NCOL == CZ*IJ
#define LN_EPS 1e-5f

// ---------------- scratch (static device globals; no allocation) -----------
__device__ float  g_x[(size_t)CM * NCOL];          // normalized msa  [c][s*i]
__device__ float  g_qkvg[(size_t)4 * CM * NCOL];   // q,k,v,g stacked [4*256][32768]
__device__ float  g_bias[(size_t)NH * IJ];         // pair bias       [h][i*j]
__device__ float  g_o[(size_t)CM * NCOL];          // gated attn out, p = c*8+h
__device__ float2 g_part[2][1024];                 // partial (sum, sumsq)
__device__ float  g_stats[4];                      // mu1, rs1, mu2, rs2

// ---------------- stage 1: partial reduction (sum, sumsq) ------------------
__global__ void __launch_bounds__(256) k_partial_reduce(const float* __restrict__ src, int which) {
    const float4* s4 = (const float4*)src;
    int t = blockIdx.x * 256 + threadIdx.x;        // 0..262143
    float s = 0.f, ss = 0.f;
#pragma unroll
    for (int k = 0; k < 8; k++) {
        float4 v = s4[t + k * 262144];
        s  += v.x + v.y + v.z + v.w;
        ss += v.x * v.x + v.y * v.y + v.z * v.z + v.w * v.w;
    }
    __shared__ float sh[256], sh2[256];
    int tid = threadIdx.x;
    sh[tid] = s; sh2[tid] = ss;
    __syncthreads();
    for (int off = 128; off; off >>= 1) {
        if (tid < off) { sh[tid] += sh[tid + off]; sh2[tid] += sh2[tid + off]; }
        __syncthreads();
    }
    if (tid == 0) g_part[which][blockIdx.x] = make_float2(sh[0], sh2[0]);
}

// ---------------- stage 2: finalize stats -----------------------------------
__global__ void __launch_bounds__(1024) k_finalize() {
    __shared__ float a0[1024], a1[1024], b0[1024], b1[1024];
    int t = threadIdx.x;
    float2 pa = g_part[0][t];
    float2 pb = g_part[1][t];
    a0[t] = pa.x; a1[t] = pa.y; b0[t] = pb.x; b1[t] = pb.y;
    __syncthreads();
    for (int off = 512; off; off >>= 1) {
        if (t < off) {
            a0[t] += a0[t + off]; a1[t] += a1[t + off];
            b0[t] += b0[t + off]; b1[t] += b1[t + off];
        }
        __syncthreads();
    }
    if (t == 0) {
        const float invN = 1.f / (float)NTOT;
        float mu1 = a0[0] * invN;
        float v1  = a1[0] * invN - mu1 * mu1;
        float mu2 = b0[0] * invN;
        float v2  = b1[0] * invN - mu2 * mu2;
        g_stats[0] = mu1; g_stats[1] = rsqrtf(v1 + LN_EPS);
        g_stats[2] = mu2; g_stats[3] = rsqrtf(v2 + LN_EPS);
    }
}

// ---------------- LN1 apply -> g_x ------------------------------------------
__global__ void __launch_bounds__(256) k_ln1(const float* __restrict__ msa,
                                             const float* __restrict__ w,
                                             const float* __restrict__ b) {
    int t = blockIdx.x * 256 + threadIdx.x;        // float4 index, 0..2097151
    float mu = g_stats[0], rs = g_stats[1];
    float4 m = ((const float4*)msa)[t];
    float4 ww = ((const float4*)w)[t];
    float4 bb = ((const float4*)b)[t];
    float4 o;
    o.x = (m.x - mu) * rs * ww.x + bb.x;
    o.y = (m.y - mu) * rs * ww.y + bb.y;
    o.z = (m.z - mu) * rs * ww.z + bb.z;
    o.w = (m.w - mu) * rs * ww.w + bb.w;
    ((float4*)g_x)[t] = o;
}

// ---------------- fused projection GEMM: [1024 x 256] @ [256 x 32768] ------
// rows 0..255 -> q, 256..511 -> k, 512..767 -> v, 768..1023 -> g (sigmoid+bg)
__global__ void __launch_bounds__(256) k_proj_gemm(const float* __restrict__ Wq,
                                                   const float* __restrict__ Wk,
                                                   const float* __restrict__ Wv,
                                                   const float* __restrict__ Wg,
                                                   const float* __restrict__ bg) {
    __shared__ float As[16][68];
    __shared__ float Bs[16][68];
    int tx = threadIdx.x, ty = threadIdx.y;
    int tid = ty * 16 + tx;
    int bm = blockIdx.y * 64, bn = blockIdx.x * 64;
    int wsel = bm >> 8;
    const float* W = (wsel == 0) ? Wq : (wsel == 1) ? Wk : (wsel == 2) ? Wv : Wg;
    int orow = bm & 255;
    float acc[4][4];
#pragma unroll
    for (int i = 0; i < 4; i++)
#pragma unroll
        for (int j = 0; j < 4; j++) acc[i][j] = 0.f;

    for (int k0 = 0; k0 < 256; k0 += 16) {
#pragma unroll
        for (int i = 0; i < 4; i++) {
            int e = tid + i * 256;
            int r = e >> 4, c = e & 15;
            As[c][r] = W[(orow + r) * 256 + k0 + c];
        }
#pragma unroll
        for (int i = 0; i < 4; i++) {
            int e = tid + i * 256;
            int cc = e >> 6, n = e & 63;
            Bs[cc][n] = g_x[(size_t)(k0 + cc) * NCOL + bn + n];
        }
        __syncthreads();
#pragma unroll
        for (int kk = 0; kk < 16; kk++) {
            float4 a4 = *(const float4*)&As[kk][ty * 4];
            float4 b4 = *(const float4*)&Bs[kk][tx * 4];
            float a[4] = {a4.x, a4.y, a4.z, a4.w};
            float b[4] = {b4.x, b4.y, b4.z, b4.w};
#pragma unroll
            for (int i = 0; i < 4; i++)
#pragma unroll
                for (int j = 0; j < 4; j++) acc[i][j] += a[i] * b[j];
        }
        __syncthreads();
    }
    bool isg = (wsel == 3);
#pragma unroll
    for (int i = 0; i < 4; i++) {
        int row = bm + ty * 4 + i;
        float bgv = isg ? bg[row & 255] : 0.f;
#pragma unroll
        for (int j = 0; j < 4; j++) {
            float v = acc[i][j];
            if (isg) v = 1.f / (1.f + __expf(-(v + bgv)));
            g_qkvg[(size_t)row * NCOL + bn + tx * 4 + j] = v;
        }
    }
}

// ---------------- pair bias: LN2 fused into Wb GEMV -------------------------
__global__ void __launch_bounds__(256) k_bias(const float* __restrict__ pair,
                                              const float* __restrict__ ln2w,
                                              const float* __restrict__ ln2b,
                                              const float* __restrict__ Wb) {
    __shared__ float wb_s[NH * CZ];
    int tid = threadIdx.x;
    for (int e = tid; e < NH * CZ; e += 256) wb_s[e] = Wb[e];
    __syncthreads();
    int col = blockIdx.x * 256 + tid;
    float mu = g_stats[2], rs = g_stats[3];
    float acc[NH];
#pragma unroll
    for (int o = 0; o < NH; o++) acc[o] = 0.f;
#pragma unroll 4
    for (int c = 0; c < CZ; c++) {
        size_t idx = (size_t)c * IJ + col;
        float z = (pair[idx] - mu) * rs * ln2w[idx] + ln2b[idx];
#pragma unroll
        for (int o = 0; o < NH; o++) acc[o] += wb_s[o * CZ + c] * z;
    }
#pragma unroll
    for (int o = 0; o < NH; o++) g_bias[(size_t)o * IJ + col] = acc[o];
}

// ---------------- attention: one block per (h, s) ---------------------------
// dyn smem: q[32][256] k[32][256] v[32][256] sc[64][260] o_s[32][64]
#define SC_STRIDE 260
#define ATTN_SMEM ((3 * 32 * 256 + 64 * SC_STRIDE + 32 * 64) * 4)

__global__ void __launch_bounds__(256, 1) k_attn() {
    extern __shared__ float sm[];
    float* q_s = sm;                  // 8192
    float* k_s = q_s + 32 * 256;      // 8192
    float* v_s = k_s + 32 * 256;      // 8192
    float* sc  = v_s + 32 * 256;      // 64*260
    float* o_s = sc + 64 * SC_STRIDE; // 2048

    int s = blockIdx.x, h = blockIdx.y;
    int tid = threadIdx.x;

    for (int e = tid; e < 32 * 256; e += 256) {
        int c = e >> 8, i = e & 255;
        size_t col = (size_t)s * 256 + i;
        q_s[e] = g_qkvg[((size_t)(0 * CM + h * 32 + c)) * NCOL + col];
        k_s[e] = g_qkvg[((size_t)(1 * CM + h * 32 + c)) * NCOL + col];
        v_s[e] = g_qkvg[((size_t)(2 * CM + h * 32 + c)) * NCOL + col];
    }
    __syncthreads();

    const float scale = 0.17677669529663687f;   // 1/sqrt(32)

    for (int i0 = 0; i0 < 256; i0 += 64) {
        // ---- scores: thread = column j, 64 rows in registers ----
        {
            int j = tid;
            float acc[64];
#pragma unroll
            for (int t = 0; t < 64; t++) acc[t] = 0.f;
#pragma unroll 4
            for (int c = 0; c < 32; c++) {
                float kv = k_s[c * 256 + j];
                const float4* q4p = (const float4*)&q_s[c * 256 + i0];
#pragma unroll
                for (int t4 = 0; t4 < 16; t4++) {
                    float4 q4 = q4p[t4];
                    acc[t4 * 4 + 0] += q4.x * kv;
                    acc[t4 * 4 + 1] += q4.y * kv;
                    acc[t4 * 4 + 2] += q4.z * kv;
                    acc[t4 * 4 + 3] += q4.w * kv;
                }
            }
#pragma unroll
            for (int t = 0; t < 64; t++) {
                float b = g_bias[(size_t)h * IJ + (size_t)(i0 + t) * 256 + j];
                sc[t * SC_STRIDE + j] = acc[t] * scale + b;
            }
        }
        __syncthreads();

        // ---- softmax rows: warp w owns rows w*8 .. w*8+7 ----
        {
            int lane = tid & 31, w = tid >> 5;
#pragma unroll
            for (int r = 0; r < 8; r++) {
                float* p = &sc[(w * 8 + r) * SC_STRIDE];
                float vals[8];
                float m = -1e30f;
#pragma unroll
                for (int u = 0; u < 8; u++) { vals[u] = p[lane + u * 32]; m = fmaxf(m, vals[u]); }
#pragma unroll
                for (int off = 16; off; off >>= 1) m = fmaxf(m, __shfl_xor_sync(0xffffffffu, m, off));
                float sum = 0.f;
#pragma unroll
                for (int u = 0; u < 8; u++) { vals[u] = __expf(vals[u] - m); sum += vals[u]; }
#pragma unroll
                for (int off = 16; off; off >>= 1) sum += __shfl_xor_sync(0xffffffffu, sum, off);
                float inv = 1.f / sum;
#pragma unroll
                for (int u = 0; u < 8; u++) p[lane + u * 32] = vals[u] * inv;
            }
        }
        __syncthreads();

        // ---- AV: thread c = tid>>3, ii = (tid&7) + 8t ----
        {
            int c = tid >> 3;
            int iw = tid & 7;
            float acc2[8];
#pragma unroll
            for (int t = 0; t < 8; t++) acc2[t] = 0.f;
#pragma unroll 4
            for (int jj = 0; jj < 256; jj += 4) {
                float4 v4 = *(const float4*)&v_s[c * 256 + jj];
#pragma unroll
                for (int t = 0; t < 8; t++) {
                    int ii = iw + t * 8;
                    float4 a4 = *(const float4*)&sc[ii * SC_STRIDE + jj];
                    acc2[t] += v4.x * a4.x + v4.y * a4.y + v4.z * a4.z + v4.w * a4.w;
                }
            }
#pragma unroll
            for (int t = 0; t < 8; t++) o_s[c * 64 + iw + t * 8] = acc2[t];
        }
        __syncthreads();

        // ---- gate + store (coalesced over i) ----
        for (int e = tid; e < 2048; e += 256) {
            int c2 = e >> 6, ii = e & 63;
            size_t col = (size_t)s * 256 + i0 + ii;
            float gv = g_qkvg[((size_t)(3 * CM + h * 32 + c2)) * NCOL + col];
            g_o[((size_t)(c2 * NH + h)) * NCOL + col] = o_s[c2 * 64 + ii] * gv;
        }
        __syncthreads();
    }
}

// ---------------- output GEMM: [256 x 256] @ [256 x 32768] + brep -----------
__global__ void __launch_bounds__(256) k_out_gemm(const float* __restrict__ Wrep,
                                                  const float* __restrict__ brep,
                                                  float* __restrict__ out) {
    __shared__ float As[16][68];
    __shared__ float Bs[16][68];
    int tx = threadIdx.x, ty = threadIdx.y;
    int tid = ty * 16 + tx;
    int bm = blockIdx.y * 64, bn = blockIdx.x * 64;
    float acc[4][4];
#pragma unroll
    for (int i = 0; i < 4; i++)
#pragma unroll
        for (int j = 0; j < 4; j++) acc[i][j] = 0.f;

    for (int k0 = 0; k0 < 256; k0 += 16) {
#pragma unroll
        for (int i = 0; i < 4; i++) {
            int e = tid + i * 256;
            int r = e >> 4, c = e & 15;
            As[c][r] = Wrep[(bm + r) * 256 + k0 + c];
        }
#pragma unroll
        for (int i = 0; i < 4; i++) {
            int e = tid + i * 256;
            int cc = e >> 6, n = e & 63;
            Bs[cc][n] = g_o[(size_t)(k0 + cc) * NCOL + bn + n];
        }
        __syncthreads();
#pragma unroll
        for (int kk = 0; kk < 16; kk++) {
            float4 a4 = *(const float4*)&As[kk][ty * 4];
            float4 b4 = *(const float4*)&Bs[kk][tx * 4];
            float a[4] = {a4.x, a4.y, a4.z, a4.w};
            float b[4] = {b4.x, b4.y, b4.z, b4.w};
#pragma unroll
            for (int i = 0; i < 4; i++)
#pragma unroll
                for (int j = 0; j < 4; j++) acc[i][j] += a[i] * b[j];
        }
        __syncthreads();
    }
#pragma unroll
    for (int i = 0; i < 4; i++) {
        int row = bm + ty * 4 + i;
        float bb = brep[row];
#pragma unroll
        for (int j = 0; j < 4; j++)
            out[(size_t)row * NCOL + bn + tx * 4 + j] = acc[i][j] + bb;
    }
}

// ---------------------------------------------------------------------------
extern "C" void kernel_launch(void* const* d_in, const int* in_sizes, int n_in,
                              void* d_out, int out_size) {
    const float* msa  = (const float*)d_in[0];
    const float* pair = (const float*)d_in[1];
    const float* ln1w = (const float*)d_in[2];
    const float* ln1b = (const float*)d_in[3];
    const float* ln2w = (const float*)d_in[4];
    const float* ln2b = (const float*)d_in[5];
    const float* Wq   = (const float*)d_in[6];
    const float* Wk   = (const float*)d_in[7];
    const float* Wv   = (const float*)d_in[8];
    const float* Wb   = (const float*)d_in[9];
    const float* Wg   = (const float*)d_in[10];
    const float* bg   = (const float*)d_in[11];
    const float* Wrep = (const float*)d_in[12];
    const float* brep = (const float*)d_in[13];
    float* out = (float*)d_out;

    // Opt-in to >48KB dynamic smem for the attention kernel. Query-then-set:
    // the set happens on the first (pre-capture) correctness call; during
    // graph capture only the (capture-safe) query runs.
    cudaFuncAttributes attr;
    cudaFuncGetAttributes(&attr, k_attn);
    if (attr.maxDynamicSharedSizeBytes < (int)ATTN_SMEM) {
        cudaFuncSetAttribute(k_attn, cudaFuncAttributeMaxDynamicSharedMemorySize, ATTN_SMEM);
    }

    k_partial_reduce<<<1024, 256>>>(msa, 0);
    k_partial_reduce<<<1024, 256>>>(pair, 1);
    k_finalize<<<1, 1024>>>();
    k_ln1<<<NTOT / 4 / 256, 256>>>(msa, ln1w, ln1b);
    k_proj_gemm<<<dim3(NCOL / 64, 1024 / 64), dim3(16, 16)>>>(Wq, Wk, Wv, Wg, bg);
    k_bias<<<IJ / 256, 256>>>(pair, ln2w, ln2b, Wb);
    k_attn<<<dim3(S_DIM, NH), 256, ATTN_SMEM>>>();
    k_out_gemm<<<dim3(NCOL / 64, 256 / 64), dim3(16, 16)>>>(Wrep, brep, out);
}

// round 3
// speedup vs baseline: 2.1112x; 2.1106x over previous
#include <cuda_runtime.h>
#include <math.h>

// ---------------------------------------------------------------------------
// RowWiseGatedAttention — tf32 mma.sync version.
// B=1, c_m=256, s=128, i=256, H=8, c_head=32, c_z=128.
// ---------------------------------------------------------------------------

#define CM     256
#define S_DIM  128
#define I_DIM  256
#define NCOL   32768            // S_DIM * I_DIM
#define CZ     128
#define IJ     65536            // I_DIM * I_DIM
#define NH     8
#define NTOT   8388608          // CM*NCOL == CZ*IJ
#define LN_EPS 1e-5f

// ---------------- scratch (static device globals; no allocation) -----------
__device__ unsigned g_x[(size_t)CM * NCOL];        // LN1(msa), tf32 bits [c][s*i]
__device__ float    g_qkvg[(size_t)4 * CM * NCOL]; // q,k,v (tf32-rounded), g (fp32)
__device__ float    g_bias[(size_t)NH * IJ];       // pair bias [h][i*j]
__device__ float    g_o[(size_t)CM * NCOL];        // gated attn out (tf32-rounded)
__device__ unsigned g_wstack[1024 * 256];          // Wq,Wk,Wv,Wg tf32 bits
__device__ unsigned g_wrep[256 * 256];             // Wrep tf32 bits
__device__ float2   g_part[2][1024];
__device__ float    g_stats[4];

// ---------------- tf32 / mma helpers ----------------------------------------
__device__ __forceinline__ unsigned f2tf(float x) {
    unsigned r; asm("cvt.rna.tf32.f32 %0, %1;" : "=r"(r) : "f"(x)); return r;
}
__device__ __forceinline__ void mma_tf32(float* c, unsigned a0, unsigned a1,
                                         unsigned a2, unsigned a3,
                                         unsigned b0, unsigned b1) {
    asm volatile(
        "mma.sync.aligned.m16n8k8.row.col.f32.tf32.tf32.f32 "
        "{%0,%1,%2,%3}, {%4,%5,%6,%7}, {%8,%9}, {%0,%1,%2,%3};"
        : "+f"(c[0]), "+f"(c[1]), "+f"(c[2]), "+f"(c[3])
        : "r"(a0), "r"(a1), "r"(a2), "r"(a3), "r"(b0), "r"(b1));
}
__device__ __forceinline__ void cpa16(unsigned saddr, const void* g) {
    asm volatile("cp.async.ca.shared.global [%0], [%1], 16;" :: "r"(saddr), "l"(g));
}

// ---------------- stage 1: partial reduction (sum, sumsq) ------------------
__global__ void __launch_bounds__(256) k_partial_reduce(const float* __restrict__ src, int which) {
    const float4* s4 = (const float4*)src;
    int t = blockIdx.x * 256 + threadIdx.x;
    float s = 0.f, ss = 0.f;
#pragma unroll
    for (int k = 0; k < 8; k++) {
        float4 v = s4[t + k * 262144];
        s  += v.x + v.y + v.z + v.w;
        ss += v.x * v.x + v.y * v.y + v.z * v.z + v.w * v.w;
    }
    __shared__ float sh[256], sh2[256];
    int tid = threadIdx.x;
    sh[tid] = s; sh2[tid] = ss;
    __syncthreads();
    for (int off = 128; off; off >>= 1) {
        if (tid < off) { sh[tid] += sh[tid + off]; sh2[tid] += sh2[tid + off]; }
        __syncthreads();
    }
    if (tid == 0) g_part[which][blockIdx.x] = make_float2(sh[0], sh2[0]);
}

__global__ void __launch_bounds__(1024) k_finalize() {
    __shared__ float a0[1024], a1[1024], b0[1024], b1[1024];
    int t = threadIdx.x;
    float2 pa = g_part[0][t];
    float2 pb = g_part[1][t];
    a0[t] = pa.x; a1[t] = pa.y; b0[t] = pb.x; b1[t] = pb.y;
    __syncthreads();
    for (int off = 512; off; off >>= 1) {
        if (t < off) {
            a0[t] += a0[t + off]; a1[t] += a1[t + off];
            b0[t] += b0[t + off]; b1[t] += b1[t + off];
        }
        __syncthreads();
    }
    if (t == 0) {
        const float invN = 1.f / (float)NTOT;
        float mu1 = a0[0] * invN;
        float v1  = a1[0] * invN - mu1 * mu1;
        float mu2 = b0[0] * invN;
        float v2  = b1[0] * invN - mu2 * mu2;
        g_stats[0] = mu1; g_stats[1] = rsqrtf(v1 + LN_EPS);
        g_stats[2] = mu2; g_stats[3] = rsqrtf(v2 + LN_EPS);
    }
}

// ---------------- LN1 apply -> g_x (tf32 bits) -------------------------------
__global__ void __launch_bounds__(256) k_ln1(const float* __restrict__ msa,
                                             const float* __restrict__ w,
                                             const float* __restrict__ b) {
    int t = blockIdx.x * 256 + threadIdx.x;
    float mu = g_stats[0], rs = g_stats[1];
    float4 m = ((const float4*)msa)[t];
    float4 ww = ((const float4*)w)[t];
    float4 bb = ((const float4*)b)[t];
    uint4 o;
    o.x = f2tf((m.x - mu) * rs * ww.x + bb.x);
    o.y = f2tf((m.y - mu) * rs * ww.y + bb.y);
    o.z = f2tf((m.z - mu) * rs * ww.z + bb.z);
    o.w = f2tf((m.w - mu) * rs * ww.w + bb.w);
    ((uint4*)g_x)[t] = o;
}

// ---------------- convert weights to tf32 bits -------------------------------
__global__ void __launch_bounds__(256) k_cvt_w(const float* __restrict__ Wq,
                                               const float* __restrict__ Wk,
                                               const float* __restrict__ Wv,
                                               const float* __restrict__ Wg,
                                               const float* __restrict__ Wrep) {
    int t = blockIdx.x * 256 + threadIdx.x;
    if (t < 262144) {
        int sel = t >> 16, off = t & 65535;
        const float* W = (sel == 0) ? Wq : (sel == 1) ? Wk : (sel == 2) ? Wv : Wg;
        g_wstack[t] = f2tf(W[off]);
    } else {
        int off = t - 262144;
        g_wrep[off] = f2tf(Wrep[off]);
    }
}

// ---------------- tf32 tensor-core GEMM: [M x 256] @ [256 x 32768] ----------
// MODE 1: proj (A=g_wstack M=1024, B=g_x, C=g_qkvg; rows<768 tf32-rounded,
//               rows>=768 sigmoid(. + bg))
// MODE 0: out  (A=g_wrep M=256, B=g_o, C=out + brep)
template<int MODE>
__global__ void __launch_bounds__(256) k_gemm(const float* __restrict__ bias,
                                              float* __restrict__ Cout) {
    __shared__ unsigned As[2][128][20];
    __shared__ unsigned Bs[2][16][136];

    const unsigned* A = MODE ? g_wstack : g_wrep;
    const unsigned* B = MODE ? g_x : (const unsigned*)g_o;
    float* C = MODE ? g_qkvg : Cout;

    const int tid = threadIdx.x;
    const int lane = tid & 31, warp = tid >> 5;
    const int wm = (warp & 1) * 64, wn = (warp >> 1) * 32;
    const int bm = blockIdx.y * 128, bn = blockIdx.x * 128;

    float acc[4][4][4];
#pragma unroll
    for (int i = 0; i < 4; i++)
#pragma unroll
        for (int j = 0; j < 4; j++)
#pragma unroll
            for (int k = 0; k < 4; k++) acc[i][j][k] = 0.f;

    unsigned sAb = (unsigned)__cvta_generic_to_shared(&As[0][0][0]);
    unsigned sBb = (unsigned)__cvta_generic_to_shared(&Bs[0][0][0]);

    auto load_tiles = [&](int buf, int k0) {
#pragma unroll
        for (int i = 0; i < 2; i++) {
            int idx = tid + i * 256;
            int row = idx >> 2, c4 = (idx & 3) << 2;
            cpa16(sAb + (((buf * 128 + row) * 20 + c4) << 2),
                  A + (size_t)(bm + row) * 256 + k0 + c4);
        }
#pragma unroll
        for (int i = 0; i < 2; i++) {
            int idx = tid + i * 256;
            int kk = idx >> 5, c4 = (idx & 31) << 2;
            cpa16(sBb + (((buf * 16 + kk) * 136 + c4) << 2),
                  B + (size_t)(k0 + kk) * NCOL + bn + c4);
        }
        asm volatile("cp.async.commit_group;" ::: "memory");
    };

    load_tiles(0, 0);
    int buf = 0;
    const int r = lane >> 2, cq = lane & 3;
    for (int it = 0; it < 16; it++) {
        asm volatile("cp.async.wait_group 0;" ::: "memory");
        __syncthreads();
        if (it < 15) load_tiles(buf ^ 1, (it + 1) * 16);
#pragma unroll
        for (int ks = 0; ks < 2; ks++) {
            int k8 = ks * 8;
            unsigned a[4][4], b[4][2];
#pragma unroll
            for (int mi = 0; mi < 4; mi++) {
                int rb = wm + mi * 16 + r;
                a[mi][0] = As[buf][rb][k8 + cq];
                a[mi][1] = As[buf][rb + 8][k8 + cq];
                a[mi][2] = As[buf][rb][k8 + cq + 4];
                a[mi][3] = As[buf][rb + 8][k8 + cq + 4];
            }
#pragma unroll
            for (int ni = 0; ni < 4; ni++) {
                int cb = wn + ni * 8 + r;
                b[ni][0] = Bs[buf][k8 + cq][cb];
                b[ni][1] = Bs[buf][k8 + 4 + cq][cb];
            }
#pragma unroll
            for (int mi = 0; mi < 4; mi++)
#pragma unroll
                for (int ni = 0; ni < 4; ni++)
                    mma_tf32(acc[mi][ni], a[mi][0], a[mi][1], a[mi][2], a[mi][3],
                             b[ni][0], b[ni][1]);
        }
        buf ^= 1;
    }

    // epilogue
#pragma unroll
    for (int mi = 0; mi < 4; mi++) {
        int row = bm + wm + mi * 16 + r;
#pragma unroll
        for (int ni = 0; ni < 4; ni++) {
            int col = bn + wn + ni * 8 + 2 * cq;
            float v0 = acc[mi][ni][0], v1 = acc[mi][ni][1];
            float v2 = acc[mi][ni][2], v3 = acc[mi][ni][3];
            if (MODE == 1) {
                if (bm >= 768) {
                    float b0 = bias[row - 768], b8 = bias[row - 768 + 8];
                    v0 = 1.f / (1.f + __expf(-(v0 + b0)));
                    v1 = 1.f / (1.f + __expf(-(v1 + b0)));
                    v2 = 1.f / (1.f + __expf(-(v2 + b8)));
                    v3 = 1.f / (1.f + __expf(-(v3 + b8)));
                } else {
                    v0 = __uint_as_float(f2tf(v0));
                    v1 = __uint_as_float(f2tf(v1));
                    v2 = __uint_as_float(f2tf(v2));
                    v3 = __uint_as_float(f2tf(v3));
                }
            } else {
                float b0 = bias[row], b8 = bias[row + 8];
                v0 += b0; v1 += b0; v2 += b8; v3 += b8;
            }
            *(float2*)&C[(size_t)row * NCOL + col]       = make_float2(v0, v1);
            *(float2*)&C[(size_t)(row + 8) * NCOL + col] = make_float2(v2, v3);
        }
    }
}

// ---------------- pair bias: LN2 fused into Wb GEMV -------------------------
__global__ void __launch_bounds__(256) k_bias(const float* __restrict__ pair,
                                              const float* __restrict__ ln2w,
                                              const float* __restrict__ ln2b,
                                              const float* __restrict__ Wb) {
    __shared__ float wb_s[NH * CZ];
    int tid = threadIdx.x;
    for (int e = tid; e < NH * CZ; e += 256) wb_s[e] = Wb[e];
    __syncthreads();
    int col = blockIdx.x * 256 + tid;
    float mu = g_stats[2], rs = g_stats[3];
    float acc[NH];
#pragma unroll
    for (int o = 0; o < NH; o++) acc[o] = 0.f;
#pragma unroll 4
    for (int c = 0; c < CZ; c++) {
        size_t idx = (size_t)c * IJ + col;
        float z = (pair[idx] - mu) * rs * ln2w[idx] + ln2b[idx];
#pragma unroll
        for (int o = 0; o < NH; o++) acc[o] += wb_s[o * CZ + c] * z;
    }
#pragma unroll
    for (int o = 0; o < NH; o++) g_bias[(size_t)o * IJ + col] = acc[o];
}

// ---------------- attention: tf32 mma, one block per (h, s) ------------------
#define QS_STR 36
#define KS_STR 264
#define VS_STR 40
#define SC_STR 260
#define OS_STR 68
#define ATTN_SMEM ((256*QS_STR + 32*KS_STR + 256*VS_STR + 64*SC_STR + 32*OS_STR) * 4)

__global__ void __launch_bounds__(256, 1) k_attn() {
    extern __shared__ unsigned smu[];
    unsigned* qs = smu;                       // [i][c] tf32 bits of q
    unsigned* ks = qs + 256 * QS_STR;         // [c][j] tf32 bits of k
    unsigned* vs = ks + 32 * KS_STR;          // [j][c] tf32 bits of v
    float*    sc = (float*)(vs + 256 * VS_STR);  // [64][SC_STR] scores/probs
    float*    os = sc + 64 * SC_STR;          // [c][i] AV out staging

    int s = blockIdx.x, h = blockIdx.y;
    int tid = threadIdx.x, lane = tid & 31, warp = tid >> 5;
    size_t colb = (size_t)s * 256;
    const unsigned* qg = (const unsigned*)g_qkvg;

    for (int e = tid; e < 8192; e += 256) {
        int c = e >> 8, i = e & 255;
        unsigned qv = qg[((size_t)(h * 32 + c)) * NCOL + colb + i];
        unsigned kv = qg[((size_t)(256 + h * 32 + c)) * NCOL + colb + i];
        unsigned vv = qg[((size_t)(512 + h * 32 + c)) * NCOL + colb + i];
        qs[i * QS_STR + c] = qv;
        ks[c * KS_STR + i] = kv;
        vs[i * VS_STR + c] = vv;
    }
    __syncthreads();

    const float scale = 0.17677669529663687f;   // 1/sqrt(32)
    const float* biasp = g_bias + (size_t)h * IJ;
    const int r = lane >> 2, cq = lane & 3;

    for (int i0 = 0; i0 < 256; i0 += 64) {
        // ---- scores = Q K^T via mma: M=64(i), N=256(j), K=32(c) ----
        {
            int wm2 = (warp & 1) * 32, wn2 = (warp >> 1) * 64;
            float acc[2][8][4];
#pragma unroll
            for (int mi = 0; mi < 2; mi++)
#pragma unroll
                for (int ni = 0; ni < 8; ni++)
#pragma unroll
                    for (int k = 0; k < 4; k++) acc[mi][ni][k] = 0.f;
#pragma unroll
            for (int k8 = 0; k8 < 32; k8 += 8) {
                unsigned a[2][4], b[8][2];
#pragma unroll
                for (int mi = 0; mi < 2; mi++) {
                    int rb = i0 + wm2 + mi * 16 + r;
                    a[mi][0] = qs[rb * QS_STR + k8 + cq];
                    a[mi][1] = qs[(rb + 8) * QS_STR + k8 + cq];
                    a[mi][2] = qs[rb * QS_STR + k8 + cq + 4];
                    a[mi][3] = qs[(rb + 8) * QS_STR + k8 + cq + 4];
                }
#pragma unroll
                for (int ni = 0; ni < 8; ni++) {
                    int cb = wn2 + ni * 8 + r;
                    b[ni][0] = ks[(k8 + cq) * KS_STR + cb];
                    b[ni][1] = ks[(k8 + 4 + cq) * KS_STR + cb];
                }
#pragma unroll
                for (int mi = 0; mi < 2; mi++)
#pragma unroll
                    for (int ni = 0; ni < 8; ni++)
                        mma_tf32(acc[mi][ni], a[mi][0], a[mi][1], a[mi][2], a[mi][3],
                                 b[ni][0], b[ni][1]);
            }
#pragma unroll
            for (int mi = 0; mi < 2; mi++) {
                int row = wm2 + mi * 16 + r;
#pragma unroll
                for (int ni = 0; ni < 8; ni++) {
                    int col = wn2 + ni * 8 + 2 * cq;
                    const float* bp  = biasp + (size_t)(i0 + row) * 256 + col;
                    const float* bp8 = bp + 8 * 256;
                    sc[row * SC_STR + col]           = acc[mi][ni][0] * scale + bp[0];
                    sc[row * SC_STR + col + 1]       = acc[mi][ni][1] * scale + bp[1];
                    sc[(row + 8) * SC_STR + col]     = acc[mi][ni][2] * scale + bp8[0];
                    sc[(row + 8) * SC_STR + col + 1] = acc[mi][ni][3] * scale + bp8[1];
                }
            }
        }
        __syncthreads();

        // ---- softmax (warp w: rows w*8..w*8+7); store tf32-rounded probs ----
        {
#pragma unroll
            for (int rr = 0; rr < 8; rr++) {
                float* p = &sc[(warp * 8 + rr) * SC_STR];
                float vals[8];
                float m = -1e30f;
#pragma unroll
                for (int u = 0; u < 8; u++) { vals[u] = p[lane + u * 32]; m = fmaxf(m, vals[u]); }
#pragma unroll
                for (int off = 16; off; off >>= 1) m = fmaxf(m, __shfl_xor_sync(0xffffffffu, m, off));
                float sum = 0.f;
#pragma unroll
                for (int u = 0; u < 8; u++) { vals[u] = __expf(vals[u] - m); sum += vals[u]; }
#pragma unroll
                for (int off = 16; off; off >>= 1) sum += __shfl_xor_sync(0xffffffffu, sum, off);
                float inv = 1.f / sum;
#pragma unroll
                for (int u = 0; u < 8; u++) p[lane + u * 32] = __uint_as_float(f2tf(vals[u] * inv));
            }
        }
        __syncthreads();

        // ---- AV via mma: M=64(i), N=32(c), K=256(j) ----
        {
            int wm2 = (warp & 1) * 32, wn2 = (warp >> 1) * 8;
            const unsigned* scu = (const unsigned*)sc;
            float acc[2][4];
#pragma unroll
            for (int mi = 0; mi < 2; mi++)
#pragma unroll
                for (int k = 0; k < 4; k++) acc[mi][k] = 0.f;
#pragma unroll 8
            for (int k8 = 0; k8 < 256; k8 += 8) {
                unsigned a[2][4], b[2];
#pragma unroll
                for (int mi = 0; mi < 2; mi++) {
                    int rb = wm2 + mi * 16 + r;
                    a[mi][0] = scu[rb * SC_STR + k8 + cq];
                    a[mi][1] = scu[(rb + 8) * SC_STR + k8 + cq];
                    a[mi][2] = scu[rb * SC_STR + k8 + cq + 4];
                    a[mi][3] = scu[(rb + 8) * SC_STR + k8 + cq + 4];
                }
                b[0] = vs[(k8 + cq) * VS_STR + wn2 + r];
                b[1] = vs[(k8 + 4 + cq) * VS_STR + wn2 + r];
                mma_tf32(acc[0], a[0][0], a[0][1], a[0][2], a[0][3], b[0], b[1]);
                mma_tf32(acc[1], a[1][0], a[1][1], a[1][2], a[1][3], b[0], b[1]);
            }
#pragma unroll
            for (int mi = 0; mi < 2; mi++) {
                int row = wm2 + mi * 16 + r;
                int col = wn2 + 2 * cq;
                os[col * OS_STR + row]           = acc[mi][0];
                os[(col + 1) * OS_STR + row]     = acc[mi][1];
                os[col * OS_STR + row + 8]       = acc[mi][2];
                os[(col + 1) * OS_STR + row + 8] = acc[mi][3];
            }
        }
        __syncthreads();

        // ---- gate + store (coalesced over i), tf32-rounded for out GEMM ----
        for (int e = tid; e < 2048; e += 256) {
            int c2 = e >> 6, ii = e & 63;
            size_t col = colb + i0 + ii;
            float gv = g_qkvg[((size_t)(768 + h * 32 + c2)) * NCOL + col];
            float ov = os[c2 * OS_STR + ii] * gv;
            g_o[((size_t)(c2 * NH + h)) * NCOL + col] = __uint_as_float(f2tf(ov));
        }
        __syncthreads();
    }
}

// ---------------------------------------------------------------------------
extern "C" void kernel_launch(void* const* d_in, const int* in_sizes, int n_in,
                              void* d_out, int out_size) {
    const float* msa  = (const float*)d_in[0];
    const float* pair = (const float*)d_in[1];
    const float* ln1w = (const float*)d_in[2];
    const float* ln1b = (const float*)d_in[3];
    const float* ln2w = (const float*)d_in[4];
    const float* ln2b = (const float*)d_in[5];
    const float* Wq   = (const float*)d_in[6];
    const float* Wk   = (const float*)d_in[7];
    const float* Wv   = (const float*)d_in[8];
    const float* Wb   = (const float*)d_in[9];
    const float* Wg   = (const float*)d_in[10];
    const float* bg   = (const float*)d_in[11];
    const float* Wrep = (const float*)d_in[12];
    const float* brep = (const float*)d_in[13];
    float* out = (float*)d_out;

    // Opt-in to >48KB dynamic smem (set happens on the pre-capture call).
    cudaFuncAttributes attr;
    cudaFuncGetAttributes(&attr, k_attn);
    if (attr.maxDynamicSharedSizeBytes < (int)ATTN_SMEM) {
        cudaFuncSetAttribute(k_attn, cudaFuncAttributeMaxDynamicSharedMemorySize, ATTN_SMEM);
    }

    k_cvt_w<<<1280, 256>>>(Wq, Wk, Wv, Wg, Wrep);
    k_partial_reduce<<<1024, 256>>>(msa, 0);
    k_partial_reduce<<<1024, 256>>>(pair, 1);
    k_finalize<<<1, 1024>>>();
    k_ln1<<<NTOT / 4 / 256, 256>>>(msa, ln1w, ln1b);
    k_gemm<1><<<dim3(256, 8), 256>>>(bg, nullptr);
    k_bias<<<IJ / 256, 256>>>(pair, ln2w, ln2b, Wb);
    k_attn<<<dim3(S_DIM, NH), 256, ATTN_SMEM>>>();
    k_gemm<0><<<dim3(256, 2), 256>>>(brep, out);
}

// round 5
// speedup vs baseline: 2.4138x; 1.1433x over previous
#include <cuda_runtime.h>
#include <math.h>

// ---------------------------------------------------------------------------
// RowWiseGatedAttention — tf32 mma.sync, merged launches, 16-warp attention.
// B=1, c_m=256, s=128, i=256, H=8, c_head=32, c_z=128.
// ---------------------------------------------------------------------------

#define CM     256
#define S_DIM  128
#define I_DIM  256
#define NCOL   32768            // S_DIM * I_DIM
#define CZ     128
#define IJ     65536            // I_DIM * I_DIM
#define NH     8
#define NTOT   8388608          // CM*NCOL == CZ*IJ
#define LN_EPS 1e-5f

// ---------------- scratch (static device globals; no allocation) -----------
__device__ unsigned g_x[(size_t)CM * NCOL];        // LN1(msa), tf32 bits [c][s*i]
__device__ float    g_qkvg[(size_t)4 * CM * NCOL]; // q,k,v (tf32-rounded), g (fp32)
__device__ float    g_bias[(size_t)NH * IJ];       // pair bias [h][i*j]
__device__ float    g_o[(size_t)CM * NCOL];        // gated attn out (tf32-rounded)
__device__ unsigned g_wstack[1024 * 256];          // Wq,Wk,Wv,Wg tf32 bits
__device__ unsigned g_wrep[256 * 256];             // Wrep tf32 bits
__device__ float2   g_part[2][1024];
__device__ float    g_stats[4];

// ---------------- tf32 / mma helpers ----------------------------------------
__device__ __forceinline__ unsigned f2tf(float x) {
    unsigned r; asm("cvt.rna.tf32.f32 %0, %1;" : "=r"(r) : "f"(x)); return r;
}
__device__ __forceinline__ void mma_tf32(float* c, unsigned a0, unsigned a1,
                                         unsigned a2, unsigned a3,
                                         unsigned b0, unsigned b1) {
    asm volatile(
        "mma.sync.aligned.m16n8k8.row.col.f32.tf32.tf32.f32 "
        "{%0,%1,%2,%3}, {%4,%5,%6,%7}, {%8,%9}, {%0,%1,%2,%3};"
        : "+f"(c[0]), "+f"(c[1]), "+f"(c[2]), "+f"(c[3])
        : "r"(a0), "r"(a1), "r"(a2), "r"(a3), "r"(b0), "r"(b1));
}
__device__ __forceinline__ void cpa16(unsigned saddr, const void* g) {
    asm volatile("cp.async.ca.shared.global [%0], [%1], 16;" :: "r"(saddr), "l"(g));
}

// ---------------- merged pre-pass: weight cvt + both partial reductions -----
__global__ void __launch_bounds__(256) k_pre(const float* __restrict__ msa,
                                             const float* __restrict__ pair,
                                             const float* __restrict__ Wq,
                                             const float* __restrict__ Wk,
                                             const float* __restrict__ Wv,
                                             const float* __restrict__ Wg,
                                             const float* __restrict__ Wrep) {
    int bid = blockIdx.x;
    if (bid >= 2048) {               // weight conversion blocks
        int t = (bid - 2048) * 256 + threadIdx.x;    // 0..327679
        if (t < 262144) {
            int sel = t >> 16, off = t & 65535;
            const float* W = (sel == 0) ? Wq : (sel == 1) ? Wk : (sel == 2) ? Wv : Wg;
            g_wstack[t] = f2tf(W[off]);
        } else {
            int off = t - 262144;
            g_wrep[off] = f2tf(Wrep[off]);
        }
        return;
    }
    int which = bid >> 10;
    const float4* s4 = (const float4*)(which ? pair : msa);
    int t = (bid & 1023) * 256 + threadIdx.x;
    float s = 0.f, ss = 0.f;
#pragma unroll
    for (int k = 0; k < 8; k++) {
        float4 v = s4[t + k * 262144];
        s  += v.x + v.y + v.z + v.w;
        ss += v.x * v.x + v.y * v.y + v.z * v.z + v.w * v.w;
    }
    __shared__ float sh[256], sh2[256];
    int tid = threadIdx.x;
    sh[tid] = s; sh2[tid] = ss;
    __syncthreads();
    for (int off = 128; off; off >>= 1) {
        if (tid < off) { sh[tid] += sh[tid + off]; sh2[tid] += sh2[tid + off]; }
        __syncthreads();
    }
    if (tid == 0) g_part[which][bid & 1023] = make_float2(sh[0], sh2[0]);
}

// ---------------- finalize stats (shuffle-based) -----------------------------
__global__ void __launch_bounds__(1024) k_finalize() {
    int t = threadIdx.x, lane = t & 31, w = t >> 5;
    float2 pa = g_part[0][t];
    float2 pb = g_part[1][t];
    float v0 = pa.x, v1 = pa.y, v2 = pb.x, v3 = pb.y;
#pragma unroll
    for (int off = 16; off; off >>= 1) {
        v0 += __shfl_xor_sync(0xffffffffu, v0, off);
        v1 += __shfl_xor_sync(0xffffffffu, v1, off);
        v2 += __shfl_xor_sync(0xffffffffu, v2, off);
        v3 += __shfl_xor_sync(0xffffffffu, v3, off);
    }
    __shared__ float sm[4][32];
    if (lane == 0) { sm[0][w] = v0; sm[1][w] = v1; sm[2][w] = v2; sm[3][w] = v3; }
    __syncthreads();
    if (w == 0) {
        v0 = sm[0][lane]; v1 = sm[1][lane]; v2 = sm[2][lane]; v3 = sm[3][lane];
#pragma unroll
        for (int off = 16; off; off >>= 1) {
            v0 += __shfl_xor_sync(0xffffffffu, v0, off);
            v1 += __shfl_xor_sync(0xffffffffu, v1, off);
            v2 += __shfl_xor_sync(0xffffffffu, v2, off);
            v3 += __shfl_xor_sync(0xffffffffu, v3, off);
        }
        if (lane == 0) {
            const float invN = 1.f / (float)NTOT;
            float mu1 = v0 * invN, var1 = v1 * invN - mu1 * mu1;
            float mu2 = v2 * invN, var2 = v3 * invN - mu2 * mu2;
            g_stats[0] = mu1; g_stats[1] = rsqrtf(var1 + LN_EPS);
            g_stats[2] = mu2; g_stats[3] = rsqrtf(var2 + LN_EPS);
        }
    }
}

// ---------------- merged LN1 apply + pair-bias GEMV -------------------------
__global__ void __launch_bounds__(256) k_ln1bias(const float* __restrict__ msa,
                                                 const float* __restrict__ w,
                                                 const float* __restrict__ b,
                                                 const float* __restrict__ pair,
                                                 const float* __restrict__ ln2w,
                                                 const float* __restrict__ ln2b,
                                                 const float* __restrict__ Wb) {
    int bid = blockIdx.x;
    if (bid < 8192) {                 // LN1 -> g_x tf32
        int t = bid * 256 + threadIdx.x;
        float mu = g_stats[0], rs = g_stats[1];
        float4 m = ((const float4*)msa)[t];
        float4 ww = ((const float4*)w)[t];
        float4 bb = ((const float4*)b)[t];
        uint4 o;
        o.x = f2tf((m.x - mu) * rs * ww.x + bb.x);
        o.y = f2tf((m.y - mu) * rs * ww.y + bb.y);
        o.z = f2tf((m.z - mu) * rs * ww.z + bb.z);
        o.w = f2tf((m.w - mu) * rs * ww.w + bb.w);
        ((uint4*)g_x)[t] = o;
        return;
    }
    // pair bias blocks: 8192..8447
    __shared__ float wb_s[NH * CZ];
    int tid = threadIdx.x;
    for (int e = tid; e < NH * CZ; e += 256) wb_s[e] = Wb[e];
    __syncthreads();
    int col = (bid - 8192) * 256 + tid;
    float mu = g_stats[2], rs = g_stats[3];
    float acc[NH];
#pragma unroll
    for (int o = 0; o < NH; o++) acc[o] = 0.f;
#pragma unroll 4
    for (int c = 0; c < CZ; c++) {
        size_t idx = (size_t)c * IJ + col;
        float z = (pair[idx] - mu) * rs * ln2w[idx] + ln2b[idx];
#pragma unroll
        for (int o = 0; o < NH; o++) acc[o] += wb_s[o * CZ + c] * z;
    }
#pragma unroll
    for (int o = 0; o < NH; o++) g_bias[(size_t)o * IJ + col] = acc[o];
}

// ---------------- tf32 tensor-core GEMM: [M x 256] @ [256 x 32768] ----------
template<int MODE>
__global__ void __launch_bounds__(256) k_gemm(const float* __restrict__ bias,
                                              float* __restrict__ Cout) {
    __shared__ unsigned As[2][128][20];
    __shared__ unsigned Bs[2][16][136];

    const unsigned* A = MODE ? g_wstack : g_wrep;
    const unsigned* B = MODE ? g_x : (const unsigned*)g_o;
    float* C = MODE ? g_qkvg : Cout;

    const int tid = threadIdx.x;
    const int lane = tid & 31, warp = tid >> 5;
    const int wm = (warp & 1) * 64, wn = (warp >> 1) * 32;
    const int bm = blockIdx.y * 128, bn = blockIdx.x * 128;

    float acc[4][4][4];
#pragma unroll
    for (int i = 0; i < 4; i++)
#pragma unroll
        for (int j = 0; j < 4; j++)
#pragma unroll
            for (int k = 0; k < 4; k++) acc[i][j][k] = 0.f;

    unsigned sAb = (unsigned)__cvta_generic_to_shared(&As[0][0][0]);
    unsigned sBb = (unsigned)__cvta_generic_to_shared(&Bs[0][0][0]);

    auto load_tiles = [&](int buf, int k0) {
#pragma unroll
        for (int i = 0; i < 2; i++) {
            int idx = tid + i * 256;
            int row = idx >> 2, c4 = (idx & 3) << 2;
            cpa16(sAb + (((buf * 128 + row) * 20 + c4) << 2),
                  A + (size_t)(bm + row) * 256 + k0 + c4);
        }
#pragma unroll
        for (int i = 0; i < 2; i++) {
            int idx = tid + i * 256;
            int kk = idx >> 5, c4 = (idx & 31) << 2;
            cpa16(sBb + (((buf * 16 + kk) * 136 + c4) << 2),
                  B + (size_t)(k0 + kk) * NCOL + bn + c4);
        }
        asm volatile("cp.async.commit_group;" ::: "memory");
    };

    load_tiles(0, 0);
    int buf = 0;
    const int r = lane >> 2, cq = lane & 3;
    for (int it = 0; it < 16; it++) {
        asm volatile("cp.async.wait_group 0;" ::: "memory");
        __syncthreads();
        if (it < 15) load_tiles(buf ^ 1, (it + 1) * 16);
#pragma unroll
        for (int ks = 0; ks < 2; ks++) {
            int k8 = ks * 8;
            unsigned a[4][4], b[4][2];
#pragma unroll
            for (int mi = 0; mi < 4; mi++) {
                int rb = wm + mi * 16 + r;
                a[mi][0] = As[buf][rb][k8 + cq];
                a[mi][1] = As[buf][rb + 8][k8 + cq];
                a[mi][2] = As[buf][rb][k8 + cq + 4];
                a[mi][3] = As[buf][rb + 8][k8 + cq + 4];
            }
#pragma unroll
            for (int ni = 0; ni < 4; ni++) {
                int cb = wn + ni * 8 + r;
                b[ni][0] = Bs[buf][k8 + cq][cb];
                b[ni][1] = Bs[buf][k8 + 4 + cq][cb];
            }
#pragma unroll
            for (int mi = 0; mi < 4; mi++)
#pragma unroll
                for (int ni = 0; ni < 4; ni++)
                    mma_tf32(acc[mi][ni], a[mi][0], a[mi][1], a[mi][2], a[mi][3],
                             b[ni][0], b[ni][1]);
        }
        buf ^= 1;
    }

#pragma unroll
    for (int mi = 0; mi < 4; mi++) {
        int row = bm + wm + mi * 16 + r;
#pragma unroll
        for (int ni = 0; ni < 4; ni++) {
            int col = bn + wn + ni * 8 + 2 * cq;
            float v0 = acc[mi][ni][0], v1 = acc[mi][ni][1];
            float v2 = acc[mi][ni][2], v3 = acc[mi][ni][3];
            if (MODE == 1) {
                if (bm >= 768) {
                    float b0 = bias[row - 768], b8 = bias[row - 768 + 8];
                    v0 = 1.f / (1.f + __expf(-(v0 + b0)));
                    v1 = 1.f / (1.f + __expf(-(v1 + b0)));
                    v2 = 1.f / (1.f + __expf(-(v2 + b8)));
                    v3 = 1.f / (1.f + __expf(-(v3 + b8)));
                } else {
                    v0 = __uint_as_float(f2tf(v0));
                    v1 = __uint_as_float(f2tf(v1));
                    v2 = __uint_as_float(f2tf(v2));
                    v3 = __uint_as_float(f2tf(v3));
                }
            } else {
                float b0 = bias[row], b8 = bias[row + 8];
                v0 += b0; v1 += b0; v2 += b8; v3 += b8;
            }
            *(float2*)&C[(size_t)row * NCOL + col]       = make_float2(v0, v1);
            *(float2*)&C[(size_t)(row + 8) * NCOL + col] = make_float2(v2, v3);
        }
    }
}

// ---------------- attention: tf32 mma, 16 warps, one block per (h, s) -------
#define QS_STR 36
#define KS_STR 264
#define VS_STR 40
#define SC_STR 260
#define OS_STR 68
#define ATTN_SMEM ((256*QS_STR + 32*KS_STR + 256*VS_STR + 64*SC_STR + 32*OS_STR) * 4)

__global__ void __launch_bounds__(512, 1) k_attn() {
    extern __shared__ unsigned smu[];
    unsigned* qs = smu;                       // [i][c] tf32 bits of q
    unsigned* ks = qs + 256 * QS_STR;         // [c][j] tf32 bits of k
    unsigned* vs = ks + 32 * KS_STR;          // [j][c] tf32 bits of v
    float*    sc = (float*)(vs + 256 * VS_STR);  // [64][SC_STR] bias/scores/probs
    float*    os = sc + 64 * SC_STR;          // [c][i] AV out staging

    int s = blockIdx.x, h = blockIdx.y;
    int tid = threadIdx.x, lane = tid & 31, warp = tid >> 5;
    size_t colb = (size_t)s * 256;
    const unsigned* qg = (const unsigned*)g_qkvg;

    for (int e = tid; e < 8192; e += 512) {
        int c = e >> 8, i = e & 255;
        unsigned qv = qg[((size_t)(h * 32 + c)) * NCOL + colb + i];
        unsigned kv = qg[((size_t)(256 + h * 32 + c)) * NCOL + colb + i];
        unsigned vv = qg[((size_t)(512 + h * 32 + c)) * NCOL + colb + i];
        qs[i * QS_STR + c] = qv;
        ks[c * KS_STR + i] = kv;
        vs[i * VS_STR + c] = vv;
    }
    __syncthreads();

    const float scale = 0.17677669529663687f;   // 1/sqrt(32)
    const float* biasp = g_bias + (size_t)h * IJ;
    const int r = lane >> 2, cq = lane & 3;
    unsigned sc_sh = (unsigned)__cvta_generic_to_shared(sc);

    for (int i0 = 0; i0 < 256; i0 += 64) {
        // ---- prefetch 64x256 bias chunk into sc via cp.async ----
        // 64*256 floats = 4096 float4s; 512 threads -> 8 iterations.
#pragma unroll
        for (int t = 0; t < 8; t++) {
            int idx = tid + t * 512;          // 0..4095 (float4 index)
            int row = idx >> 6, c4 = (idx & 63) << 2;
            cpa16(sc_sh + ((row * SC_STR + c4) << 2),
                  biasp + (size_t)(i0 + row) * 256 + c4);
        }
        asm volatile("cp.async.commit_group;" ::: "memory");

        // ---- scores = Q K^T via mma: M=64(i), N=256(j), K=32(c) ----
        int wm2 = (warp & 3) * 16, wn2 = (warp >> 2) * 64;
        float acc[8][4];
#pragma unroll
        for (int ni = 0; ni < 8; ni++)
#pragma unroll
            for (int k = 0; k < 4; k++) acc[ni][k] = 0.f;
#pragma unroll
        for (int k8 = 0; k8 < 32; k8 += 8) {
            unsigned a[4], b[8][2];
            int rb = i0 + wm2 + r;
            a[0] = qs[rb * QS_STR + k8 + cq];
            a[1] = qs[(rb + 8) * QS_STR + k8 + cq];
            a[2] = qs[rb * QS_STR + k8 + cq + 4];
            a[3] = qs[(rb + 8) * QS_STR + k8 + cq + 4];
#pragma unroll
            for (int ni = 0; ni < 8; ni++) {
                int cb = wn2 + ni * 8 + r;
                b[ni][0] = ks[(k8 + cq) * KS_STR + cb];
                b[ni][1] = ks[(k8 + 4 + cq) * KS_STR + cb];
            }
#pragma unroll
            for (int ni = 0; ni < 8; ni++)
                mma_tf32(acc[ni], a[0], a[1], a[2], a[3], b[ni][0], b[ni][1]);
        }
        asm volatile("cp.async.wait_group 0;" ::: "memory");
        __syncthreads();
        // epilogue: scores*scale + preloaded bias (RMW in smem)
#pragma unroll
        for (int ni = 0; ni < 8; ni++) {
            int row = wm2 + r;
            int col = wn2 + ni * 8 + 2 * cq;
            float* p0 = &sc[row * SC_STR + col];
            float* p8 = &sc[(row + 8) * SC_STR + col];
            p0[0] = acc[ni][0] * scale + p0[0];
            p0[1] = acc[ni][1] * scale + p0[1];
            p8[0] = acc[ni][2] * scale + p8[0];
            p8[1] = acc[ni][3] * scale + p8[1];
        }
        __syncthreads();

        // ---- softmax (warp w: rows w*4..w*4+3); store tf32-rounded probs ----
#pragma unroll
        for (int rr = 0; rr < 4; rr++) {
            float* p = &sc[(warp * 4 + rr) * SC_STR];
            float vals[8];
            float m = -1e30f;
#pragma unroll
            for (int u = 0; u < 8; u++) { vals[u] = p[lane + u * 32]; m = fmaxf(m, vals[u]); }
#pragma unroll
            for (int off = 16; off; off >>= 1) m = fmaxf(m, __shfl_xor_sync(0xffffffffu, m, off));
            float sum = 0.f;
#pragma unroll
            for (int u = 0; u < 8; u++) { vals[u] = __expf(vals[u] - m); sum += vals[u]; }
#pragma unroll
            for (int off = 16; off; off >>= 1) sum += __shfl_xor_sync(0xffffffffu, sum, off);
            float inv = 1.f / sum;
#pragma unroll
            for (int u = 0; u < 8; u++) p[lane + u * 32] = __uint_as_float(f2tf(vals[u] * inv));
        }
        __syncthreads();

        // ---- AV via mma: M=64(i), N=32(c), K=256(j) ----
        {
            int am = (warp & 3) * 16, an = (warp >> 2) * 8;
            const unsigned* scu = (const unsigned*)sc;
            float av[4] = {0.f, 0.f, 0.f, 0.f};
#pragma unroll 8
            for (int k8 = 0; k8 < 256; k8 += 8) {
                unsigned a[4], b[2];
                int rb = am + r;
                a[0] = scu[rb * SC_STR + k8 + cq];
                a[1] = scu[(rb + 8) * SC_STR + k8 + cq];
                a[2] = scu[rb * SC_STR + k8 + cq + 4];
                a[3] = scu[(rb + 8) * SC_STR + k8 + cq + 4];
                b[0] = vs[(k8 + cq) * VS_STR + an + r];
                b[1] = vs[(k8 + 4 + cq) * VS_STR + an + r];
                mma_tf32(av, a[0], a[1], a[2], a[3], b[0], b[1]);
            }
            int row = am + r, col = an + 2 * cq;
            os[col * OS_STR + row]           = av[0];
            os[(col + 1) * OS_STR + row]     = av[1];
            os[col * OS_STR + row + 8]       = av[2];
            os[(col + 1) * OS_STR + row + 8] = av[3];
        }
        __syncthreads();

        // ---- gate + store (coalesced over i), tf32-rounded for out GEMM ----
        for (int e = tid; e < 2048; e += 512) {
            int c2 = e >> 6, ii = e & 63;
            size_t col = colb + i0 + ii;
            float gv = g_qkvg[((size_t)(768 + h * 32 + c2)) * NCOL + col];
            float ov = os[c2 * OS_STR + ii] * gv;
            g_o[((size_t)(c2 * NH + h)) * NCOL + col] = __uint_as_float(f2tf(ov));
        }
        __syncthreads();
    }
}

// ---------------------------------------------------------------------------
extern "C" void kernel_launch(void* const* d_in, const int* in_sizes, int n_in,
                              void* d_out, int out_size) {
    const float* msa  = (const float*)d_in[0];
    const float* pair = (const float*)d_in[1];
    const float* ln1w = (const float*)d_in[2];
    const float* ln1b = (const float*)d_in[3];
    const float* ln2w = (const float*)d_in[4];
    const float* ln2b = (const float*)d_in[5];
    const float* Wq   = (const float*)d_in[6];
    const float* Wk   = (const float*)d_in[7];
    const float* Wv   = (const float*)d_in[8];
    const float* Wb   = (const float*)d_in[9];
    const float* Wg   = (const float*)d_in[10];
    const float* bg   = (const float*)d_in[11];
    const float* Wrep = (const float*)d_in[12];
    const float* brep = (const float*)d_in[13];
    float* out = (float*)d_out;

    // Opt-in to >48KB dynamic smem (set happens on the pre-capture call).
    cudaFuncAttributes attr;
    cudaFuncGetAttributes(&attr, k_attn);
    if (attr.maxDynamicSharedSizeBytes < (int)ATTN_SMEM) {
        cudaFuncSetAttribute(k_attn, cudaFuncAttributeMaxDynamicSharedMemorySize, ATTN_SMEM);
    }

    k_pre<<<2048 + 1280, 256>>>(msa, pair, Wq, Wk, Wv, Wg, Wrep);
    k_finalize<<<1, 1024>>>();
    k_ln1bias<<<8192 + 256, 256>>>(msa, ln1w, ln1b, pair, ln2w, ln2b, Wb);
    k_gemm<1><<<dim3(256, 8), 256>>>(bg, nullptr);
    k_attn<<<dim3(S_DIM, NH), 512, ATTN_SMEM>>>();
    k_gemm<0><<<dim3(256, 2), 256>>>(brep, out);
}